// round 16
// baseline (speedup 1.0000x reference)
#include <cuda_runtime.h>
#include <math.h>

#define NN 100000
#define EE 3200000
#define K_SEL 11111
#define LN_EPS 1e-5f
#define TB 256
#define GN ((NN + TB - 1) / TB)     // 391
#define GE (EE / TB)                // 12500
#define SCAN_B 512
#define NBLK ((NN + SCAN_B - 1) / SCAN_B)   // 196

// ---------------- scratch (device globals; no allocation) ----------------
__device__ __align__(16) uint4  g_edge[EE];    // SORTED by dst: {src, dst, norm_bits, 0}
__device__ __align__(16) int    g_ts[EE];
__device__ __align__(16) int    g_td[EE];
__device__ __align__(16) float  g_tw[EE];
__device__ __align__(16) int    g_scnt[NN];
__device__ __align__(16) int    g_cur[NN];
__device__ __align__(16) int    g_bsum[NBLK];
__device__ __align__(16) float  g_deg[NN];
__device__ __align__(16) float  g_sA[NN];
__device__ __align__(16) float  g_sB[NN];
__device__ __align__(16) float  g_sC[NN];
__device__ __align__(16) float  g_f0[NN * 8];
__device__ __align__(16) float  g_f1[NN * 8];
__device__ __align__(16) float  g_f2[NN * 8];
__device__ __align__(16) float  g_acc[NN * 8];
__device__ __align__(16) float  g_h[NN];
__device__ double   g_red[2];
__device__ unsigned g_hist[256];
__device__ unsigned g_tick[8];
__device__ unsigned g_prefix;
__device__ unsigned g_krem;
__device__ float    g_thresh;
__device__ unsigned g_cnt2[2];                 // n_gt, n_tie
__device__ int      g_is64;
__device__ unsigned char g_tiemark[NN];

// ---------------- helpers ----------------
__device__ __forceinline__ float* sel_s(int s) {
    switch (s) { case 1: return g_sA; case 2: return g_sB; case 3: return g_sC; default: return g_h; }
}
__device__ __forceinline__ float* sel_f(int s) {
    switch (s) { case 0: return g_f0; case 1: return g_f1; default: return g_f2; }
}

__device__ __forceinline__ void red_add_v4(float* p, float4 v) {
    asm volatile("red.global.add.v4.f32 [%0], {%1, %2, %3, %4};"
                 :: "l"(p), "f"(v.x), "f"(v.y), "f"(v.z), "f"(v.w) : "memory");
}
__device__ __forceinline__ void red_add_f32(float* p, float v) {
    asm volatile("red.global.add.f32 [%0], %1;" :: "l"(p), "f"(v) : "memory");
}
__device__ __forceinline__ unsigned desc_key(float x) {
    unsigned u = __float_as_uint(x);
    unsigned asc = (u & 0x80000000u) ? ~u : (u | 0x80000000u);
    return ~asc;
}

// scalar segmented scatter (dst-sorted): one RED per dst-run per warp
__device__ __forceinline__ void seg_scat1(const float* __restrict__ sp,
                                          float* __restrict__ dp, int e, int lane) {
    uint4 ev = __ldg(&g_edge[e]);
    int d = (int)ev.y;
    float v = __uint_as_float(ev.z) * __ldg(&sp[ev.x]);
    #pragma unroll
    for (int o = 1; o < 32; o <<= 1) {
        float t = __shfl_up_sync(0xffffffffu, v, o);
        int  td = __shfl_up_sync(0xffffffffu, d, o);
        if (lane >= o && td == d) v += t;
    }
    int nd = __shfl_down_sync(0xffffffffu, d, 1);
    if (lane == 31 || nd != d) red_add_f32(&dp[d], v);
}

// 8-channel segmented scatter
__device__ __forceinline__ void seg_scat8(const float* __restrict__ s,
                                          float* __restrict__ dmem, int e, int lane) {
    uint4 ev = __ldg(&g_edge[e]);
    float nrm = __uint_as_float(ev.z);
    int d = (int)ev.y;
    const float4* sp = reinterpret_cast<const float4*>(s + (size_t)ev.x * 8);
    float4 a = __ldg(sp), b = __ldg(sp + 1);
    a.x *= nrm; a.y *= nrm; a.z *= nrm; a.w *= nrm;
    b.x *= nrm; b.y *= nrm; b.z *= nrm; b.w *= nrm;
    #pragma unroll
    for (int o = 1; o < 32; o <<= 1) {
        int  td = __shfl_up_sync(0xffffffffu, d, o);
        float t0 = __shfl_up_sync(0xffffffffu, a.x, o);
        float t1 = __shfl_up_sync(0xffffffffu, a.y, o);
        float t2 = __shfl_up_sync(0xffffffffu, a.z, o);
        float t3 = __shfl_up_sync(0xffffffffu, a.w, o);
        float t4 = __shfl_up_sync(0xffffffffu, b.x, o);
        float t5 = __shfl_up_sync(0xffffffffu, b.y, o);
        float t6 = __shfl_up_sync(0xffffffffu, b.z, o);
        float t7 = __shfl_up_sync(0xffffffffu, b.w, o);
        if (lane >= o && td == d) {
            a.x += t0; a.y += t1; a.z += t2; a.w += t3;
            b.x += t4; b.y += t5; b.z += t6; b.w += t7;
        }
    }
    int nd = __shfl_down_sync(0xffffffffu, d, 1);
    if (lane == 31 || nd != d) {
        float* dp = dmem + (size_t)d * 8;
        red_add_v4(dp, a);
        red_add_v4(dp + 4, b);
    }
}

// pick body (runs in last block of fused hist kernels); sh = 256 counts
__device__ __forceinline__ void pick_body(int b, const unsigned* sh) {
    unsigned krem = g_krem, cum = 0u;
    int j = 0;
    for (; j < 256; j++) { unsigned c = sh[j]; if (cum + c >= krem) break; cum += c; }
    if (j > 255) j = 255;
    g_krem = krem - cum;
    unsigned prefix = g_prefix | ((unsigned)j << (b * 8));
    g_prefix = prefix;
    if (b == 0) {
        unsigned asc = ~prefix;
        unsigned u = (asc & 0x80000000u) ? (asc ^ 0x80000000u) : ~asc;
        g_thresh = __uint_as_float(u);
    }
}

// ---------------- setup ----------------
// init + dtype detect (block 0)
__global__ void k_init(const int* __restrict__ ei32) {
    int i = blockIdx.x * TB + threadIdx.x;
    if (i < NN) {
        g_deg[i] = 0.f; g_scnt[i] = 0;
        g_sA[i] = 0.f; g_sB[i] = 0.f; g_sC[i] = 0.f;
        float4 z = make_float4(0.f, 0.f, 0.f, 0.f);
        reinterpret_cast<float4*>(g_f1 + (size_t)i * 8)[0] = z;
        reinterpret_cast<float4*>(g_f1 + (size_t)i * 8)[1] = z;
        reinterpret_cast<float4*>(g_f2 + (size_t)i * 8)[0] = z;
        reinterpret_cast<float4*>(g_f2 + (size_t)i * 8)[1] = z;
    }
    if (i < 256) g_hist[i] = 0u;
    if (i < 8) g_tick[i] = 0u;
    if (i == 0) {
        g_red[0] = 0.0; g_red[1] = 0.0;
        g_prefix = 0u; g_krem = (unsigned)K_SEL;
        g_cnt2[0] = 0u; g_cnt2[1] = 0u;
    }
    if (blockIdx.x == 0) {
        __shared__ int bad;
        if (threadIdx.x == 0) bad = 0;
        __syncthreads();
        for (int k = threadIdx.x; k < 512; k += TB)
            if (ei32[2 * k + 1] != 0) bad = 1;
        __syncthreads();
        if (threadIdx.x == 0) g_is64 = bad ? 0 : 1;
    }
}

__global__ void k_prep(const void* __restrict__ eiv, const float* __restrict__ attr) {
    int e = blockIdx.x * TB + threadIdx.x;
    int s, d;
    if (g_is64) {
        const long long* ei = (const long long*)eiv;
        s = (int)ei[e]; d = (int)ei[EE + e];
    } else {
        const int* ei = (const int*)eiv;
        s = ei[e]; d = ei[EE + e];
    }
    s = min(max(s, 0), NN - 1);
    d = min(max(d, 0), NN - 1);
    float w = fabsf(attr[e]);
    g_ts[e] = s; g_td[e] = d; g_tw[e] = w;
    atomicAdd(&g_scnt[d], 1);
    red_add_f32(&g_deg[d], w);
}

// scan part 1 + dinv fused
__global__ void k_scan1() {
    __shared__ int sh[SCAN_B];
    int i = blockIdx.x * SCAN_B + threadIdx.x;
    int v = (i < NN) ? g_scnt[i] : 0;
    if (i < NN) {                       // fused dinv
        float dg = g_deg[i];
        g_deg[i] = (dg > 0.f) ? rsqrtf(dg) : 0.f;
    }
    sh[threadIdx.x] = v;
    __syncthreads();
    for (int o = 1; o < SCAN_B; o <<= 1) {
        int t = (threadIdx.x >= o) ? sh[threadIdx.x - o] : 0;
        __syncthreads();
        sh[threadIdx.x] += t;
        __syncthreads();
    }
    if (i < NN) g_cur[i] = sh[threadIdx.x] - v;
    if (threadIdx.x == SCAN_B - 1) g_bsum[blockIdx.x] = sh[threadIdx.x];
}

__global__ void k_scan2() {   // <<<1,256>>>
    __shared__ int sh[256];
    int t = threadIdx.x;
    int v = (t < NBLK) ? g_bsum[t] : 0;
    sh[t] = v;
    __syncthreads();
    for (int o = 1; o < 256; o <<= 1) {
        int x = (t >= o) ? sh[t - o] : 0;
        __syncthreads();
        sh[t] += x;
        __syncthreads();
    }
    if (t < NBLK) g_bsum[t] = sh[t] - v;
}

__global__ void k_scan3() {
    int i = blockIdx.x * TB + threadIdx.x;
    if (i < NN) g_cur[i] += g_bsum[i / SCAN_B];
}

// counting-sort fill (edge blocks) + l1 init (node blocks)
__global__ void k_fill_l1init(const float* __restrict__ x, const float* __restrict__ W1) {
    if (blockIdx.x < GN) {
        int n = blockIdx.x * TB + threadIdx.x;
        if (n >= NN) return;
        float xv = x[n];
        #pragma unroll
        for (int j = 0; j < 8; j++) g_acc[n * 8 + j] = xv * __ldg(&W1[j]);
    } else {
        int e = (blockIdx.x - GN) * TB + threadIdx.x;
        int s = g_ts[e], d = g_td[e];
        float w = g_tw[e];
        int pos = atomicAdd(&g_cur[d], 1);
        float nv = __ldg(&g_deg[s]) * w * __ldg(&g_deg[d]);
        g_edge[pos] = make_uint4((unsigned)s, (unsigned)d, __float_as_uint(nv), 0u);
    }
}

// ---------------- hop kernels ----------------
__global__ void k_scat1x(const float* __restrict__ x) {   // x -> sA
    int e = blockIdx.x * TB + threadIdx.x;
    seg_scat1(x, g_sA, e, threadIdx.x & 31);
}

// fused: node acc += sel_s(ss)*W1[hop,:]  |  edge: sel_s(ds) += A sel_s(ss)
__global__ void k_l1hop(int ss, int ds, int hop, const float* __restrict__ W1) {
    if (blockIdx.x < GN) {
        int n = blockIdx.x * TB + threadIdx.x;
        if (n >= NN) return;
        float sv = sel_s(ss)[n];
        #pragma unroll
        for (int j = 0; j < 8; j++) g_acc[n * 8 + j] += sv * __ldg(&W1[hop * 8 + j]);
    } else {
        int e = (blockIdx.x - GN) * TB + threadIdx.x;
        seg_scat1(sel_s(ss), sel_s(ds), e, threadIdx.x & 31);
    }
}

__global__ void k_l1_final(const float* __restrict__ W1, const float* __restrict__ b1,
                           const float* __restrict__ W2) {
    int n = blockIdx.x * TB + threadIdx.x;
    if (n >= NN) return;
    float sv = g_sC[n];
    float v[8];
    #pragma unroll
    for (int j = 0; j < 8; j++) {
        float a = g_acc[n * 8 + j] + sv * __ldg(&W1[24 + j]) + __ldg(&b1[j]);
        v[j] = fmaxf(a, 0.f);
        g_f0[n * 8 + j] = v[j];
    }
    #pragma unroll
    for (int c = 0; c < 8; c++) {
        float a = 0.f;
        #pragma unroll
        for (int r = 0; r < 8; r++) a += v[r] * __ldg(&W2[r * 8 + c]);
        g_acc[n * 8 + c] = a;
    }
}

// fused layer-2 hop. nodeBlocks = 0 (edge-only) or GN.
// node: acc += f[sf]@W2[hopi]; optionally zero f[zf]. edge: f[df] += A f[sf]
__global__ void k_l2hop(int nodeBlocks, int sf, int df, int hopi, int zf,
                        const float* __restrict__ W2) {
    if ((int)blockIdx.x < nodeBlocks) {
        int n = blockIdx.x * TB + threadIdx.x;
        if (n >= NN) return;
        const float* hop = sel_f(sf);
        float hv[8];
        #pragma unroll
        for (int r = 0; r < 8; r++) hv[r] = hop[n * 8 + r];
        const float* w = W2 + hopi * 64;
        #pragma unroll
        for (int c = 0; c < 8; c++) {
            float a = g_acc[n * 8 + c];
            #pragma unroll
            for (int r = 0; r < 8; r++) a += hv[r] * __ldg(&w[r * 8 + c]);
            g_acc[n * 8 + c] = a;
        }
        if (zf >= 0) {
            float4 z = make_float4(0.f, 0.f, 0.f, 0.f);
            reinterpret_cast<float4*>(sel_f(zf) + (size_t)n * 8)[0] = z;
            reinterpret_cast<float4*>(sel_f(zf) + (size_t)n * 8)[1] = z;
        }
    } else {
        int e = (blockIdx.x - nodeBlocks) * TB + threadIdx.x;
        seg_scat8(sel_f(sf), sel_f(df), e, threadIdx.x & 31);
    }
}

// layer2 finish: v = relu(acc + f0@W2[3] + b2)
// seed Horner buffers: g_h=z0, sA=z3 (src), sB=z2 (seed), sC=z1 (seed)
__global__ void k_l2_final(const float* __restrict__ W2, const float* __restrict__ b2,
                           const float* __restrict__ W3) {
    int n = blockIdx.x * TB + threadIdx.x;
    if (n >= NN) return;
    float hv[8];
    #pragma unroll
    for (int r = 0; r < 8; r++) hv[r] = g_f0[n * 8 + r];
    float z0 = 0.f, z1 = 0.f, z2 = 0.f, z3 = 0.f;
    #pragma unroll
    for (int c = 0; c < 8; c++) {
        float a = g_acc[n * 8 + c] + __ldg(&b2[c]);
        #pragma unroll
        for (int r = 0; r < 8; r++) a += hv[r] * __ldg(&W2[192 + r * 8 + c]);
        float v = fmaxf(a, 0.f);
        z0 += v * __ldg(&W3[c]);
        z1 += v * __ldg(&W3[8 + c]);
        z2 += v * __ldg(&W3[16 + c]);
        z3 += v * __ldg(&W3[24 + c]);
    }
    g_h[n] = z0;
    g_sA[n] = z3;
    g_sB[n] = z2;
    g_sC[n] = z1;
}

// plain scalar scatter between sel_s buffers (Horner steps; targets pre-seeded)
__global__ void k_hscat(int ss, int ds) {
    int e = blockIdx.x * TB + threadIdx.x;
    seg_scat1(sel_s(ss), sel_s(ds), e, threadIdx.x & 31);
}

// layer3 finish: g_h = relu(g_h + b3); reduce sum/sumsq
__global__ void k_l3_final(const float* __restrict__ b3) {
    int n = blockIdx.x * TB + threadIdx.x;
    float v = 0.f;
    if (n < NN) {
        v = fmaxf(g_h[n] + __ldg(b3), 0.f);
        g_h[n] = v;
    }
    __shared__ double ss[TB], sq[TB];
    ss[threadIdx.x] = (double)v;
    sq[threadIdx.x] = (double)v * (double)v;
    __syncthreads();
    for (int off = TB / 2; off > 0; off >>= 1) {
        if (threadIdx.x < off) {
            ss[threadIdx.x] += ss[threadIdx.x + off];
            sq[threadIdx.x] += sq[threadIdx.x + off];
        }
        __syncthreads();
    }
    if (threadIdx.x == 0) {
        atomicAdd(&g_red[0], ss[0]);
        atomicAdd(&g_red[1], sq[0]);
    }
}

// ---------------- fused select ----------------
// standardize + write out[:,0] + histogram byte 3 + last-block pick
__global__ void k_normhist(float* __restrict__ out) {
    __shared__ unsigned sh[256];
    sh[threadIdx.x] = 0u;
    __syncthreads();
    int n = blockIdx.x * TB + threadIdx.x;
    if (n < NN) {
        double mu = g_red[0] / (double)NN;
        double var = g_red[1] / (double)NN - mu * mu;
        float muf = (float)mu;
        float inv = rsqrtf((float)var + LN_EPS);
        float hn = (g_h[n] - muf) * inv;
        g_h[n] = hn;
        out[2 * n] = hn;
        atomicAdd(&sh[desc_key(hn) >> 24], 1u);
    }
    __syncthreads();
    if (sh[threadIdx.x]) atomicAdd(&g_hist[threadIdx.x], sh[threadIdx.x]);
    __threadfence();
    __shared__ int isLast;
    __syncthreads();
    if (threadIdx.x == 0) isLast = (atomicAdd(&g_tick[4], 1u) == (unsigned)(gridDim.x - 1));
    __syncthreads();
    if (isLast) {
        unsigned v = atomicExch(&g_hist[threadIdx.x], 0u);
        sh[threadIdx.x] = v;
        __syncthreads();
        if (threadIdx.x == 0) pick_body(3, sh);
    }
}

// histogram byte b (with prefix filter) + last-block pick
__global__ void k_histp(int b) {
    __shared__ unsigned sh[256];
    sh[threadIdx.x] = 0u;
    __syncthreads();
    unsigned prefix = g_prefix;
    unsigned maskHigh = 0xFFFFFFFFu << ((b + 1) * 8);
    for (int i = blockIdx.x * TB + threadIdx.x; i < NN; i += gridDim.x * TB) {
        unsigned d = desc_key(g_h[i]);
        if (((d ^ prefix) & maskHigh) == 0u)
            atomicAdd(&sh[(d >> (b * 8)) & 0xFFu], 1u);
    }
    __syncthreads();
    if (sh[threadIdx.x]) atomicAdd(&g_hist[threadIdx.x], sh[threadIdx.x]);
    __threadfence();
    __shared__ int isLast;
    __syncthreads();
    if (threadIdx.x == 0) isLast = (atomicAdd(&g_tick[b], 1u) == (unsigned)(gridDim.x - 1));
    __syncthreads();
    if (isLast) {
        unsigned v = atomicExch(&g_hist[threadIdx.x], 0u);
        sh[threadIdx.x] = v;
        __syncthreads();
        if (threadIdx.x == 0) pick_body(b, sh);
    }
}

// count gt/tie + (rare) last-block stable tie-ranking
__global__ void k_counttie() {
    int n = blockIdx.x * TB + threadIdx.x;
    float th = g_thresh;
    if (n < NN) {
        float x = g_h[n];
        if (x > th) atomicAdd(&g_cnt2[0], 1u);
        else if (x == th) atomicAdd(&g_cnt2[1], 1u);
    }
    __threadfence();
    __shared__ int isLast;
    __syncthreads();
    if (threadIdx.x == 0) isLast = (atomicAdd(&g_tick[5], 1u) == (unsigned)(gridDim.x - 1));
    __syncthreads();
    if (!isLast) return;
    unsigned gt = atomicAdd(&g_cnt2[0], 0u);
    unsigned tie = atomicAdd(&g_cnt2[1], 0u);
    int r = K_SEL - (int)gt;
    if ((int)tie == r) return;          // no ambiguity: all ties selected
    __shared__ unsigned warpsum[8], woff[8];
    __shared__ unsigned s_running;
    if (threadIdx.x == 0) s_running = 0u;
    __syncthreads();
    int lane = threadIdx.x & 31, w = threadIdx.x >> 5;
    for (int base = 0; base < NN; base += TB) {
        int i = base + threadIdx.x;
        bool f = (i < NN) && (g_h[i] == th);
        unsigned bal = __ballot_sync(0xffffffffu, f);
        unsigned pre = __popc(bal & ((1u << lane) - 1u));
        if (lane == 0) warpsum[w] = __popc(bal);
        __syncthreads();
        if (threadIdx.x == 0) {
            unsigned run = s_running;
            #pragma unroll
            for (int j = 0; j < 8; j++) { woff[j] = run; run += warpsum[j]; }
            s_running = run;
        }
        __syncthreads();
        if (f) g_tiemark[i] = ((woff[w] + pre) < (unsigned)r) ? 1 : 0;
        __syncthreads();
    }
}

__global__ void k_final(float* __restrict__ out) {
    int i = blockIdx.x * TB + threadIdx.x;
    if (i >= NN) return;
    float hn = g_h[i], th = g_thresh;
    int r = K_SEL - (int)g_cnt2[0];
    int nt = (int)g_cnt2[1];
    bool inset;
    if (hn > th) inset = true;
    else if (hn == th) inset = (nt == r) ? true : (g_tiemark[i] != 0);
    else inset = false;
    float z = hn - fabsf(th) + (inset ? 0.1f : -0.1f);
    out[2 * i + 1] = 1.f / (1.f + expf(-z));
}

// ---------------- launch ----------------
extern "C" void kernel_launch(void* const* d_in, const int* in_sizes, int n_in,
                              void* d_out, int out_size) {
    const float* x    = (const float*)d_in[0];
    const float* attr = (const float*)d_in[1];
    const float* W1   = (const float*)d_in[2];
    const float* b1   = (const float*)d_in[3];
    const float* W2   = (const float*)d_in[4];
    const float* b2   = (const float*)d_in[5];
    const float* W3   = (const float*)d_in[6];
    const float* b3   = (const float*)d_in[7];
    const void*  ei   = d_in[8];
    float* out = (float*)d_out;

    const int GNE = GN + GE;

    k_init<<<GN, TB>>>((const int*)ei);
    k_prep<<<GE, TB>>>(ei, attr);
    k_scan1<<<NBLK, SCAN_B>>>();
    k_scan2<<<1, 256>>>();
    k_scan3<<<GN, TB>>>();
    k_fill_l1init<<<GNE, TB>>>(x, W1);      // sorted edges + acc = x*W1[0]

    // ---- layer 1 (1 -> 8) ----
    k_scat1x<<<GE, TB>>>(x);                // sA = A x
    k_l1hop<<<GNE, TB>>>(1, 2, 1, W1);      // acc += sA*W1[1] | sB = A sA
    k_l1hop<<<GNE, TB>>>(2, 3, 2, W1);      // acc += sB*W1[2] | sC = A sB
    k_l1_final<<<GN, TB>>>(W1, b1, W2);     // f0 = relu(acc + sC*W1[3] + b1); acc = f0@W2[0]

    // ---- layer 2 (8 -> 8) ----
    k_l2hop<<<GE,  TB>>>(0, 0, 1, -1, -1, W2);   // f1 = A f0
    k_l2hop<<<GNE, TB>>>(GN, 1, 2, 1, 0, W2);    // acc += f1@W2[1], zero f0 | f2 = A f1
    k_l2hop<<<GNE, TB>>>(GN, 2, 0, 2, -1, W2);   // acc += f2@W2[2]          | f0 = A f2
    k_l2_final<<<GN, TB>>>(W2, b2, W3);          // g_h=z0; sA=z3; sB=z2(seed); sC=z1(seed)

    // ---- layer 3 (8 -> 1) seeded Horner: h = z0 + A(z1 + A(z2 + A z3)) ----
    k_hscat<<<GE, TB>>>(1, 2);              // sB = z2 + A z3
    k_hscat<<<GE, TB>>>(2, 3);              // sC = z1 + A sB
    k_hscat<<<GE, TB>>>(3, 5);              // g_h = z0 + A sC
    k_l3_final<<<GN, TB>>>(b3);             // g_h = relu(g_h + b3); reduce

    // ---- standardize + out[:,0] + fused radix select ----
    k_normhist<<<GN, TB>>>(out);            // + hist b=3 + pick
    k_histp<<<148, TB>>>(2);
    k_histp<<<148, TB>>>(1);
    k_histp<<<148, TB>>>(0);
    k_counttie<<<GN, TB>>>();
    k_final<<<GN, TB>>>(out);
}

// round 17
// speedup vs baseline: 1.1733x; 1.1733x over previous
#include <cuda_runtime.h>
#include <math.h>

#define NN 100000
#define EE 3200000
#define K_SEL 11111
#define LN_EPS 1e-5f

#define SCAN_B 512
#define NBLK ((NN + SCAN_B - 1) / SCAN_B)   // 196

// ---------------- scratch (device globals; no allocation) ----------------
__device__ __align__(16) uint4  g_edge[EE];    // SORTED by dst: {src, dst, norm_bits, 0}
__device__ __align__(16) int    g_scnt[NN];    // per-dst count
__device__ __align__(16) int    g_cur[NN];     // sort cursor
__device__ __align__(16) int    g_bsum[NBLK];
__device__ __align__(16) float  g_deg[NN];     // deg then dinv (in place)
__device__ __align__(16) float  g_sA[NN];
__device__ __align__(16) float  g_sB[NN];
__device__ __align__(16) float  g_sC[NN];
__device__ __align__(16) float  g_sD[NN];
__device__ __align__(16) float  g_f0[NN * 8];
__device__ __align__(16) float  g_f1[NN * 8];
__device__ __align__(16) float  g_acc[NN * 8];
__device__ __align__(16) float  g_h[NN];
__device__ double   g_red[2];                  // sum, sumsq
__device__ unsigned g_hist[256];
__device__ unsigned g_prefix;
__device__ unsigned g_krem;
__device__ float    g_thresh;
__device__ unsigned g_cnt2[2];                 // n_gt, n_tie
__device__ int      g_is64;
__device__ unsigned char g_tiemark[NN];

// ---------------- helpers ----------------
__device__ __forceinline__ float* sel_s(int s) {
    switch (s) {
        case 1: return g_sA;
        case 2: return g_sB;
        case 3: return g_sC;
        default: return g_sD;
    }
}

__device__ __forceinline__ void red_add_v4(float* p, float4 v) {
    asm volatile("red.global.add.v4.f32 [%0], {%1, %2, %3, %4};"
                 :: "l"(p), "f"(v.x), "f"(v.y), "f"(v.z), "f"(v.w) : "memory");
}

__device__ __forceinline__ void red_add_f32(float* p, float v) {
    asm volatile("red.global.add.f32 [%0], %1;" :: "l"(p), "f"(v) : "memory");
}

__device__ __forceinline__ unsigned desc_key(float x) {
    unsigned u = __float_as_uint(x);
    unsigned asc = (u & 0x80000000u) ? ~u : (u | 0x80000000u);
    return ~asc;
}

// one segmented scan + RED for a (dst, val) pair held by this lane
__device__ __forceinline__ void scan_red(float* __restrict__ dp, int d, float v, int lane) {
    #pragma unroll
    for (int o = 1; o < 32; o <<= 1) {
        float t = __shfl_up_sync(0xffffffffu, v, o);
        int  td = __shfl_up_sync(0xffffffffu, d, o);
        if (lane >= o && td == d) v += t;
    }
    int nd = __shfl_down_sync(0xffffffffu, d, 1);
    if (lane == 31 || nd != d) red_add_f32(&dp[d], v);
}

// batched x4 scalar segmented scatter: warp owns 128 consecutive sorted edges.
// 4 independent edge loads, then 4 independent gathers (MLP=4), then 4 scans.
__device__ __forceinline__ void seg_scat1_b4(const float* __restrict__ sp,
                                             float* __restrict__ dp) {
    int w = (blockIdx.x * blockDim.x + threadIdx.x) >> 5;
    int lane = threadIdx.x & 31;
    int base = w * 128 + lane;
    uint4 e0 = __ldg(&g_edge[base]);
    uint4 e1 = __ldg(&g_edge[base + 32]);
    uint4 e2 = __ldg(&g_edge[base + 64]);
    uint4 e3 = __ldg(&g_edge[base + 96]);
    float v0 = __uint_as_float(e0.z) * __ldg(&sp[e0.x]);
    float v1 = __uint_as_float(e1.z) * __ldg(&sp[e1.x]);
    float v2 = __uint_as_float(e2.z) * __ldg(&sp[e2.x]);
    float v3 = __uint_as_float(e3.z) * __ldg(&sp[e3.x]);
    scan_red(dp, (int)e0.y, v0, lane);
    scan_red(dp, (int)e1.y, v1, lane);
    scan_red(dp, (int)e2.y, v2, lane);
    scan_red(dp, (int)e3.y, v3, lane);
}

// ---------------- setup ----------------
__global__ void k_detect(const int* __restrict__ ei32) {
    __shared__ int bad;
    if (threadIdx.x == 0) bad = 0;
    __syncthreads();
    for (int i = threadIdx.x; i < 512; i += blockDim.x)
        if (ei32[2 * i + 1] != 0) bad = 1;
    __syncthreads();
    if (threadIdx.x == 0) g_is64 = bad ? 0 : 1;
}

__global__ void k_init() {
    int i = blockIdx.x * blockDim.x + threadIdx.x;
    if (i < NN) { g_deg[i] = 0.f; g_scnt[i] = 0; }
    if (i < 256) g_hist[i] = 0u;
    if (i == 0) {
        g_red[0] = 0.0; g_red[1] = 0.0;
        g_prefix = 0u; g_krem = (unsigned)K_SEL;
        g_cnt2[0] = 0u; g_cnt2[1] = 0u;
    }
}

// count per-dst (for sort) + weighted degree (for norm). No staging writes.
__global__ void k_prep(const void* __restrict__ eiv, const float* __restrict__ attr) {
    int e = blockIdx.x * blockDim.x + threadIdx.x;   // EE divisible by block
    int d;
    if (g_is64) {
        const long long* ei = (const long long*)eiv;
        d = (int)ei[EE + e];
    } else {
        const int* ei = (const int*)eiv;
        d = ei[EE + e];
    }
    d = min(max(d, 0), NN - 1);
    float w = fabsf(attr[e]);
    atomicAdd(&g_scnt[d], 1);
    red_add_f32(&g_deg[d], w);
}

__global__ void k_dinv() {
    int i = blockIdx.x * blockDim.x + threadIdx.x;
    if (i >= NN) return;
    float dg = g_deg[i];
    g_deg[i] = (dg > 0.f) ? rsqrtf(dg) : 0.f;
}

// ---------------- prefix scan over g_scnt -> g_cur ----------------
__global__ void k_scan1() {
    __shared__ int sh[SCAN_B];
    int i = blockIdx.x * SCAN_B + threadIdx.x;
    int v = (i < NN) ? g_scnt[i] : 0;
    sh[threadIdx.x] = v;
    __syncthreads();
    for (int o = 1; o < SCAN_B; o <<= 1) {
        int t = (threadIdx.x >= o) ? sh[threadIdx.x - o] : 0;
        __syncthreads();
        sh[threadIdx.x] += t;
        __syncthreads();
    }
    if (i < NN) g_cur[i] = sh[threadIdx.x] - v;
    if (threadIdx.x == SCAN_B - 1) g_bsum[blockIdx.x] = sh[threadIdx.x];
}

__global__ void k_scan2() {   // <<<1,256>>>
    __shared__ int sh[256];
    int t = threadIdx.x;
    int v = (t < NBLK) ? g_bsum[t] : 0;
    sh[t] = v;
    __syncthreads();
    for (int o = 1; o < 256; o <<= 1) {
        int x = (t >= o) ? sh[t - o] : 0;
        __syncthreads();
        sh[t] += x;
        __syncthreads();
    }
    if (t < NBLK) g_bsum[t] = sh[t] - v;
}

__global__ void k_scan3() {
    int i = blockIdx.x * blockDim.x + threadIdx.x;
    if (i < NN) g_cur[i] += g_bsum[i / SCAN_B];
}

// counting-sort fill (by dst): re-decode inputs, compute final norm, write record
__global__ void k_fill(const void* __restrict__ eiv, const float* __restrict__ attr) {
    int e = blockIdx.x * blockDim.x + threadIdx.x;
    int s, d;
    if (g_is64) {
        const long long* ei = (const long long*)eiv;
        s = (int)ei[e]; d = (int)ei[EE + e];
    } else {
        const int* ei = (const int*)eiv;
        s = ei[e]; d = ei[EE + e];
    }
    s = min(max(s, 0), NN - 1);
    d = min(max(d, 0), NN - 1);
    float w = fabsf(attr[e]);
    int pos = atomicAdd(&g_cur[d], 1);
    float nv = __ldg(&g_deg[s]) * w * __ldg(&g_deg[d]);
    g_edge[pos] = make_uint4((unsigned)s, (unsigned)d, __float_as_uint(nv), 0u);
}

// ---------------- hop scatters ----------------
__global__ void k_scat1x(const float* __restrict__ x) {
    seg_scat1_b4(x, g_sA);
}

__global__ void k_scat1(int ssel, int dsel) {
    seg_scat1_b4(sel_s(ssel), sel_s(dsel));
}

// 8-channel: d[dst,:] += norm * s[src,:], segmented scan across 8 channels
__global__ void k_scat8(int dir) {  // dir 0: f0->f1, 1: f1->f0
    int e = blockIdx.x * blockDim.x + threadIdx.x;
    int lane = threadIdx.x & 31;
    uint4 ev = __ldg(&g_edge[e]);
    const float* s = dir ? g_f1 : g_f0;
    float* dmem = dir ? g_f0 : g_f1;
    float nrm = __uint_as_float(ev.z);
    int d = (int)ev.y;
    const float4* sp = reinterpret_cast<const float4*>(s + (size_t)ev.x * 8);
    float4 a = __ldg(sp), b = __ldg(sp + 1);
    a.x *= nrm; a.y *= nrm; a.z *= nrm; a.w *= nrm;
    b.x *= nrm; b.y *= nrm; b.z *= nrm; b.w *= nrm;
    #pragma unroll
    for (int o = 1; o < 32; o <<= 1) {
        int  td = __shfl_up_sync(0xffffffffu, d, o);
        float t0 = __shfl_up_sync(0xffffffffu, a.x, o);
        float t1 = __shfl_up_sync(0xffffffffu, a.y, o);
        float t2 = __shfl_up_sync(0xffffffffu, a.z, o);
        float t3 = __shfl_up_sync(0xffffffffu, a.w, o);
        float t4 = __shfl_up_sync(0xffffffffu, b.x, o);
        float t5 = __shfl_up_sync(0xffffffffu, b.y, o);
        float t6 = __shfl_up_sync(0xffffffffu, b.z, o);
        float t7 = __shfl_up_sync(0xffffffffu, b.w, o);
        if (lane >= o && td == d) {
            a.x += t0; a.y += t1; a.z += t2; a.w += t3;
            b.x += t4; b.y += t5; b.z += t6; b.w += t7;
        }
    }
    int nd = __shfl_down_sync(0xffffffffu, d, 1);
    if (lane == 31 || nd != d) {
        float* dp = dmem + (size_t)d * 8;
        red_add_v4(dp, a);
        red_add_v4(dp + 4, b);
    }
}

// ---------------- node kernels ----------------
__global__ void k_l1_init(const float* __restrict__ x, const float* __restrict__ W1) {
    int n = blockIdx.x * blockDim.x + threadIdx.x;
    if (n >= NN) return;
    float xv = x[n];
    #pragma unroll
    for (int j = 0; j < 8; j++) g_acc[n * 8 + j] = xv * __ldg(&W1[j]);
    g_sA[n] = 0.f;
}

__global__ void k_l1_acc(int ssel, int hop, int zsel, const float* __restrict__ W1) {
    int n = blockIdx.x * blockDim.x + threadIdx.x;
    if (n >= NN) return;
    float sv = sel_s(ssel)[n];
    #pragma unroll
    for (int j = 0; j < 8; j++) g_acc[n * 8 + j] += sv * __ldg(&W1[hop * 8 + j]);
    sel_s(zsel)[n] = 0.f;
}

__global__ void k_l1_final(int ssel, const float* __restrict__ W1,
                           const float* __restrict__ b1, const float* __restrict__ W2) {
    int n = blockIdx.x * blockDim.x + threadIdx.x;
    if (n >= NN) return;
    float sv = sel_s(ssel)[n];
    float v[8];
    #pragma unroll
    for (int j = 0; j < 8; j++) {
        float a = g_acc[n * 8 + j] + sv * __ldg(&W1[24 + j]) + __ldg(&b1[j]);
        v[j] = fmaxf(a, 0.f);
        g_f0[n * 8 + j] = v[j];
    }
    #pragma unroll
    for (int c = 0; c < 8; c++) {
        float a = 0.f;
        #pragma unroll
        for (int r = 0; r < 8; r++) a += v[r] * __ldg(&W2[r * 8 + c]);
        g_acc[n * 8 + c] = a;
    }
    float4 z = make_float4(0.f, 0.f, 0.f, 0.f);
    reinterpret_cast<float4*>(g_f1 + (size_t)n * 8)[0] = z;
    reinterpret_cast<float4*>(g_f1 + (size_t)n * 8)[1] = z;
}

__global__ void k_l2_acc(int dir, int hopi, const float* __restrict__ W2) {
    int n = blockIdx.x * blockDim.x + threadIdx.x;
    if (n >= NN) return;
    const float* hop = dir ? g_f1 : g_f0;
    float* zb = dir ? g_f0 : g_f1;
    float hv[8];
    #pragma unroll
    for (int r = 0; r < 8; r++) hv[r] = hop[n * 8 + r];
    const float* w = W2 + hopi * 64;
    #pragma unroll
    for (int c = 0; c < 8; c++) {
        float a = g_acc[n * 8 + c];
        #pragma unroll
        for (int r = 0; r < 8; r++) a += hv[r] * __ldg(&w[r * 8 + c]);
        g_acc[n * 8 + c] = a;
    }
    float4 z = make_float4(0.f, 0.f, 0.f, 0.f);
    reinterpret_cast<float4*>(zb + (size_t)n * 8)[0] = z;
    reinterpret_cast<float4*>(zb + (size_t)n * 8)[1] = z;
}

__global__ void k_l2_final(const float* __restrict__ W2, const float* __restrict__ b2,
                           const float* __restrict__ W3) {
    int n = blockIdx.x * blockDim.x + threadIdx.x;
    if (n >= NN) return;
    float hv[8];
    #pragma unroll
    for (int r = 0; r < 8; r++) hv[r] = g_f1[n * 8 + r];
    float z0 = 0.f, z1 = 0.f, z2 = 0.f, z3 = 0.f;
    #pragma unroll
    for (int c = 0; c < 8; c++) {
        float a = g_acc[n * 8 + c] + __ldg(&b2[c]);
        #pragma unroll
        for (int r = 0; r < 8; r++) a += hv[r] * __ldg(&W2[192 + r * 8 + c]);
        float v = fmaxf(a, 0.f);
        z0 += v * __ldg(&W3[c]);
        z1 += v * __ldg(&W3[8 + c]);
        z2 += v * __ldg(&W3[16 + c]);
        z3 += v * __ldg(&W3[24 + c]);
    }
    g_h[n] = z0;
    g_sA[n] = z1;
    g_sB[n] = z2;
    g_sC[n] = z3;
    g_sD[n] = 0.f;
}

__global__ void k_haux(int dsel, int asel, int zsel) {
    int n = blockIdx.x * blockDim.x + threadIdx.x;
    if (n >= NN) return;
    sel_s(dsel)[n] += sel_s(asel)[n];
    sel_s(zsel)[n] = 0.f;
}

__global__ void k_l3_final(const float* __restrict__ b3) {
    int n = blockIdx.x * blockDim.x + threadIdx.x;
    float v = 0.f;
    if (n < NN) {
        v = fmaxf(g_h[n] + g_sB[n] + __ldg(b3), 0.f);
        g_h[n] = v;
    }
    __shared__ double ss[256], sq[256];
    ss[threadIdx.x] = (double)v;
    sq[threadIdx.x] = (double)v * (double)v;
    __syncthreads();
    for (int off = 128; off > 0; off >>= 1) {
        if (threadIdx.x < off) {
            ss[threadIdx.x] += ss[threadIdx.x + off];
            sq[threadIdx.x] += sq[threadIdx.x + off];
        }
        __syncthreads();
    }
    if (threadIdx.x == 0) {
        atomicAdd(&g_red[0], ss[0]);
        atomicAdd(&g_red[1], sq[0]);
    }
}

__global__ void k_normout(float* __restrict__ out) {
    int n = blockIdx.x * blockDim.x + threadIdx.x;
    if (n >= NN) return;
    double mu = g_red[0] / (double)NN;
    double var = g_red[1] / (double)NN - mu * mu;
    float muf = (float)mu;
    float inv = rsqrtf((float)var + LN_EPS);
    float hn = (g_h[n] - muf) * inv;
    g_h[n] = hn;
    out[2 * n] = hn;
}

// ---------------- radix select ----------------
__global__ void k_hist(int b) {
    __shared__ unsigned sh[256];
    for (int i = threadIdx.x; i < 256; i += blockDim.x) sh[i] = 0u;
    __syncthreads();
    unsigned prefix = g_prefix;
    unsigned maskHigh = (b == 3) ? 0u : (0xFFFFFFFFu << ((b + 1) * 8));
    for (int i = blockIdx.x * blockDim.x + threadIdx.x; i < NN; i += gridDim.x * blockDim.x) {
        unsigned d = desc_key(g_h[i]);
        if (((d ^ prefix) & maskHigh) == 0u)
            atomicAdd(&sh[(d >> (b * 8)) & 0xFFu], 1u);
    }
    __syncthreads();
    for (int i = threadIdx.x; i < 256; i += blockDim.x)
        if (sh[i]) atomicAdd(&g_hist[i], sh[i]);
}

__global__ void k_pick(int b) {  // <<<1,256>>>
    __shared__ unsigned sh[256];
    int t = threadIdx.x;
    sh[t] = g_hist[t];
    g_hist[t] = 0u;
    __syncthreads();
    if (t == 0) {
        unsigned krem = g_krem, cum = 0u;
        int j = 0;
        for (; j < 256; j++) {
            if (cum + sh[j] >= krem) break;
            cum += sh[j];
        }
        if (j > 255) j = 255;
        g_krem = krem - cum;
        unsigned prefix = g_prefix | ((unsigned)j << (b * 8));
        g_prefix = prefix;
        if (b == 0) {
            unsigned asc = ~prefix;
            unsigned u = (asc & 0x80000000u) ? (asc ^ 0x80000000u) : ~asc;
            g_thresh = __uint_as_float(u);
        }
    }
}

__global__ void k_count() {
    int i = blockIdx.x * blockDim.x + threadIdx.x;
    if (i >= NN) return;
    float x = g_h[i], th = g_thresh;
    if (x > th) atomicAdd(&g_cnt2[0], 1u);
    else if (x == th) atomicAdd(&g_cnt2[1], 1u);
}

__global__ void k_tiemark() {   // <<<1,1024>>>
    int r = K_SEL - (int)g_cnt2[0];
    int t = (int)g_cnt2[1];
    if (t == r) return;
    float th = g_thresh;
    __shared__ unsigned warpsum[32];
    __shared__ unsigned woff[32];
    __shared__ unsigned s_running;
    if (threadIdx.x == 0) s_running = 0u;
    __syncthreads();
    int lane = threadIdx.x & 31, w = threadIdx.x >> 5;
    for (int base = 0; base < NN; base += (int)blockDim.x) {
        int i = base + threadIdx.x;
        bool f = (i < NN) && (g_h[i] == th);
        unsigned bal = __ballot_sync(0xFFFFFFFFu, f);
        unsigned pre = __popc(bal & ((1u << lane) - 1u));
        if (lane == 0) warpsum[w] = __popc(bal);
        __syncthreads();
        if (threadIdx.x == 0) {
            unsigned run = s_running;
            for (int j = 0; j < 32; j++) { woff[j] = run; run += warpsum[j]; }
            s_running = run;
        }
        __syncthreads();
        if (f) {
            unsigned rank = woff[w] + pre;
            g_tiemark[i] = (rank < (unsigned)r) ? 1 : 0;
        }
        __syncthreads();
    }
}

__global__ void k_final(float* __restrict__ out) {
    int i = blockIdx.x * blockDim.x + threadIdx.x;
    if (i >= NN) return;
    float hn = g_h[i], th = g_thresh;
    int r = K_SEL - (int)g_cnt2[0];
    int nt = (int)g_cnt2[1];
    bool inset;
    if (hn > th) inset = true;
    else if (hn == th) inset = (nt == r) ? true : (g_tiemark[i] != 0);
    else inset = false;
    float z = hn - fabsf(th) + (inset ? 0.1f : -0.1f);
    out[2 * i + 1] = 1.f / (1.f + expf(-z));
}

// ---------------- launch ----------------
extern "C" void kernel_launch(void* const* d_in, const int* in_sizes, int n_in,
                              void* d_out, int out_size) {
    const float* x    = (const float*)d_in[0];
    const float* attr = (const float*)d_in[1];
    const float* W1   = (const float*)d_in[2];
    const float* b1   = (const float*)d_in[3];
    const float* W2   = (const float*)d_in[4];
    const float* b2   = (const float*)d_in[5];
    const float* W3   = (const float*)d_in[6];
    const float* b3   = (const float*)d_in[7];
    const void*  ei   = d_in[8];
    float* out = (float*)d_out;

    const int TB = 256;
    const int gN  = (NN + TB - 1) / TB;
    const int gE  = EE / TB;            // per-edge kernels (12500)
    const int gE4 = EE / (TB * 4);      // batched x4 scalar kernels (3125)

    k_detect<<<1, 256>>>((const int*)ei);
    k_init<<<gN, TB>>>();
    k_prep<<<gE, TB>>>(ei, attr);
    k_dinv<<<gN, TB>>>();
    k_scan1<<<NBLK, SCAN_B>>>();
    k_scan2<<<1, 256>>>();
    k_scan3<<<gN, TB>>>();
    k_fill<<<gE, TB>>>(ei, attr);       // dst-sorted edge table with final norm

    // ---- layer 1 (1 -> 8), scalar hops (batched x4) ----
    k_l1_init<<<gN, TB>>>(x, W1);           // acc = x*W1[0], zero sA
    k_scat1x<<<gE4, TB>>>(x);               // sA = A x
    k_l1_acc<<<gN, TB>>>(1, 1, 2, W1);      // acc += sA*W1[1], zero sB
    k_scat1<<<gE4, TB>>>(1, 2);             // sB = A sA
    k_l1_acc<<<gN, TB>>>(2, 2, 1, W1);      // acc += sB*W1[2], zero sA
    k_scat1<<<gE4, TB>>>(2, 1);             // sA = A sB
    k_l1_final<<<gN, TB>>>(1, W1, b1, W2);  // f0 = relu(...); acc = f0@W2[0]; zero f1

    // ---- layer 2 (8 -> 8), vector hops ----
    k_scat8<<<gE, TB>>>(0);                 // f1 = A f0
    k_l2_acc<<<gN, TB>>>(1, 1, W2);         // acc += f1@W2[1], zero f0
    k_scat8<<<gE, TB>>>(1);                 // f0 = A f1
    k_l2_acc<<<gN, TB>>>(0, 2, W2);         // acc += f0@W2[2], zero f1
    k_scat8<<<gE, TB>>>(0);                 // f1 = A f0
    k_l2_final<<<gN, TB>>>(W2, b2, W3);     // v=relu(...); g_h=z0; sA..sC=z1..z3; zero sD

    // ---- layer 3 (8 -> 1) via Horner on scalars: y = z0 + A(z1 + A(z2 + A z3)) ----
    k_scat1<<<gE4, TB>>>(3, 4);             // sD = A sC  (A z3)
    k_haux<<<gN, TB>>>(4, 2, 3);            // sD += sB (z2); zero sC
    k_scat1<<<gE4, TB>>>(4, 3);             // sC = A sD
    k_haux<<<gN, TB>>>(3, 1, 2);            // sC += sA (z1); zero sB
    k_scat1<<<gE4, TB>>>(3, 2);             // sB = A sC
    k_l3_final<<<gN, TB>>>(b3);             // g_h = relu(g_h + sB + b3); reduce

    // ---- standardize + output col 0 ----
    k_normout<<<gN, TB>>>(out);

    // ---- radix select k-th largest ----
    for (int b = 3; b >= 0; b--) {
        k_hist<<<256, 256>>>(b);
        k_pick<<<1, 256>>>(b);
    }
    k_count<<<gN, TB>>>();
    k_tiemark<<<1, 1024>>>();
    k_final<<<gN, TB>>>(out);
}